// round 1
// baseline (speedup 1.0000x reference)
#include <cuda_runtime.h>
#include <math.h>

// Problem constants
#define BB 4
#define SS 2048
#define DD 1024
#define M_TOT (BB * SS)   // 8192

// ----- device scratch (no allocations allowed in kernel_launch) -----
__device__ float g_Q[M_TOT * DD];          // 33.5 MB
__device__ float g_K[M_TOT * DD];          // 33.5 MB
__device__ float g_V[M_TOT * DD];          // 33.5 MB
__device__ float g_P[BB * SS * SS];        // 67 MB (scores -> probs in place)
__device__ float g_ent[M_TOT];             // per-row entropy

// ======================================================================
// Generic 128x128 tile GEMM, BK=8, 256 threads, 8x8 per-thread microtile.
// A is row-major M x KDIM (lda == KDIM).
// If BT: B operand is row-major N x KDIM (C = A * B^T). Else: K x N (C = A*B).
// C[m,n] = alpha * sum_k A[m,k]*B(.,.) + bias[n]
// ======================================================================
template <int KDIM, bool BT>
__device__ __forceinline__ void gemm128(
    const float* __restrict__ A,
    const float* __restrict__ Bm, int ldb,
    float* __restrict__ C, int ldc,
    const float* __restrict__ bias, float alpha)
{
    __shared__ float As[8][132];
    __shared__ float Bs[8][132];

    const int tid = threadIdx.x;
    const int m0 = blockIdx.y * 128;
    const int n0 = blockIdx.x * 128;
    const int tx = tid & 15;        // 0..15 -> 8 cols each
    const int ty = tid >> 4;        // 0..15 -> 8 rows each

    float acc[8][8];
#pragma unroll
    for (int i = 0; i < 8; i++)
#pragma unroll
        for (int j = 0; j < 8; j++) acc[i][j] = 0.0f;

    const int ar = tid >> 1;            // 0..127
    const int ac = (tid & 1) * 4;       // 0 or 4

#pragma unroll 1
    for (int k0 = 0; k0 < KDIM; k0 += 8) {
        // A tile: 128 rows x 8 k, transposed store
        float4 av = *(const float4*)(A + (size_t)(m0 + ar) * KDIM + k0 + ac);
        As[ac + 0][ar] = av.x;
        As[ac + 1][ar] = av.y;
        As[ac + 2][ar] = av.z;
        As[ac + 3][ar] = av.w;

        if (BT) {
            // B tile: rows are n, cols are k -> transpose like A
            float4 bv = *(const float4*)(Bm + (size_t)(n0 + ar) * ldb + k0 + ac);
            Bs[ac + 0][ar] = bv.x;
            Bs[ac + 1][ar] = bv.y;
            Bs[ac + 2][ar] = bv.z;
            Bs[ac + 3][ar] = bv.w;
        } else {
            // B tile: 8 k-rows x 128 n, direct store
            const int br = tid >> 5;           // 0..7
            const int bc = (tid & 31) * 4;     // 0..124
            float4 bv = *(const float4*)(Bm + (size_t)(k0 + br) * ldb + n0 + bc);
            *(float4*)&Bs[br][bc] = bv;
        }
        __syncthreads();

#pragma unroll
        for (int k = 0; k < 8; k++) {
            float af[8], bf[8];
            float4 a0 = *(const float4*)&As[k][ty * 8];
            float4 a1 = *(const float4*)&As[k][ty * 8 + 4];
            float4 b0 = *(const float4*)&Bs[k][tx * 8];
            float4 b1 = *(const float4*)&Bs[k][tx * 8 + 4];
            af[0] = a0.x; af[1] = a0.y; af[2] = a0.z; af[3] = a0.w;
            af[4] = a1.x; af[5] = a1.y; af[6] = a1.z; af[7] = a1.w;
            bf[0] = b0.x; bf[1] = b0.y; bf[2] = b0.z; bf[3] = b0.w;
            bf[4] = b1.x; bf[5] = b1.y; bf[6] = b1.z; bf[7] = b1.w;
#pragma unroll
            for (int i = 0; i < 8; i++)
#pragma unroll
                for (int j = 0; j < 8; j++)
                    acc[i][j] = fmaf(af[i], bf[j], acc[i][j]);
        }
        __syncthreads();
    }

    // epilogue
#pragma unroll
    for (int i = 0; i < 8; i++) {
        const int m = m0 + ty * 8 + i;
#pragma unroll
        for (int j = 0; j < 8; j += 4) {
            const int n = n0 + tx * 8 + j;
            float4 v;
            v.x = acc[i][j + 0] * alpha + (bias ? bias[n + 0] : 0.0f);
            v.y = acc[i][j + 1] * alpha + (bias ? bias[n + 1] : 0.0f);
            v.z = acc[i][j + 2] * alpha + (bias ? bias[n + 2] : 0.0f);
            v.w = acc[i][j + 3] * alpha + (bias ? bias[n + 3] : 0.0f);
            *(float4*)(C + (size_t)m * ldc + n) = v;
        }
    }
}

// ----- stage 1: Q/K/V projections (blockIdx.z selects which) -----
__global__ __launch_bounds__(256) void k_qkv(
    const float* __restrict__ x,
    const float* __restrict__ Wq, const float* __restrict__ bq,
    const float* __restrict__ Wk, const float* __restrict__ bk,
    const float* __restrict__ Wv, const float* __restrict__ bv)
{
    const float* W; const float* b; float* out;
    if (blockIdx.z == 0)      { W = Wq; b = bq; out = g_Q; }
    else if (blockIdx.z == 1) { W = Wk; b = bk; out = g_K; }
    else                      { W = Wv; b = bv; out = g_V; }
    gemm128<DD, false>(x, W, DD, out, DD, b, 1.0f);
}

// ----- stage 2: scores = (Q K^T) / 8 / temperature -----
__global__ __launch_bounds__(256) void k_scores(const float* __restrict__ temp)
{
    const int bz = blockIdx.z;
    const float alpha = 0.125f / temp[0];   // 1/sqrt(HEAD_DIM=64) = 1/8
    gemm128<DD, true>(g_Q + (size_t)bz * SS * DD, g_K + (size_t)bz * SS * DD, DD,
                      g_P + (size_t)bz * SS * SS, SS, nullptr, alpha);
}

// ----- reductions -----
__device__ __forceinline__ float warp_sum(float v) {
#pragma unroll
    for (int o = 16; o; o >>= 1) v += __shfl_xor_sync(0xffffffffu, v, o);
    return v;
}
__device__ __forceinline__ float warp_max(float v) {
#pragma unroll
    for (int o = 16; o; o >>= 1) v = fmaxf(v, __shfl_xor_sync(0xffffffffu, v, o));
    return v;
}
__device__ __forceinline__ float block_sum(float v, float* sh) {
    const int lane = threadIdx.x & 31, w = threadIdx.x >> 5;
    v = warp_sum(v);
    if (lane == 0) sh[w] = v;
    __syncthreads();
    if (w == 0) {
        float r = (lane < 8) ? sh[lane] : 0.0f;
        r = warp_sum(r);
        if (lane == 0) sh[0] = r;
    }
    __syncthreads();
    float r = sh[0];
    __syncthreads();
    return r;
}
__device__ __forceinline__ float block_max(float v, float* sh) {
    const int lane = threadIdx.x & 31, w = threadIdx.x >> 5;
    v = warp_max(v);
    if (lane == 0) sh[w] = v;
    __syncthreads();
    if (w == 0) {
        float r = (lane < 8) ? sh[lane] : -INFINITY;
        r = warp_max(r);
        if (lane == 0) sh[0] = r;
    }
    __syncthreads();
    float r = sh[0];
    __syncthreads();
    return r;
}

// ----- stage 3: softmax + per-row entropy (one block per row) -----
__global__ __launch_bounds__(256) void k_softmax()
{
    __shared__ float sh[8];
    const int row = blockIdx.x;              // 0..8191
    float* p = g_P + (size_t)row * SS;
    const int tid = threadIdx.x;

    float v[8];
#pragma unroll
    for (int j = 0; j < 8; j++) v[j] = p[tid + j * 256];

    float m = -INFINITY;
#pragma unroll
    for (int j = 0; j < 8; j++) m = fmaxf(m, v[j]);
    m = block_max(m, sh);

    float l = 0.0f, t = 0.0f;
#pragma unroll
    for (int j = 0; j < 8; j++) {
        float e = expf(v[j] - m);
        l += e;
        t += e * v[j];
        v[j] = e;
    }
    l = block_sum(l, sh);
    t = block_sum(t, sh);

    const float inv = 1.0f / l;
#pragma unroll
    for (int j = 0; j < 8; j++) p[tid + j * 256] = v[j] * inv;

    if (tid == 0)
        g_ent[row] = (m + logf(l)) - t * inv;   // = -sum p log p
}

// ----- stage 4: O = P @ V -> d_out -----
__global__ __launch_bounds__(256) void k_pv(float* __restrict__ out)
{
    const int bz = blockIdx.z;
    gemm128<SS, false>(g_P + (size_t)bz * SS * SS,
                       g_V + (size_t)bz * SS * DD, DD,
                       out + (size_t)bz * SS * DD, DD, nullptr, 1.0f);
}

// ----- stage 5: entropy mean -> last output element -----
__global__ __launch_bounds__(256) void k_entmean(float* __restrict__ out, int out_size)
{
    __shared__ float sh[8];
    float s = 0.0f;
    for (int i = threadIdx.x; i < M_TOT; i += 256) s += g_ent[i];
    s = block_sum(s, sh);
    if (threadIdx.x == 0) out[out_size - 1] = s * (1.0f / M_TOT);
}

extern "C" void kernel_launch(void* const* d_in, const int* in_sizes, int n_in,
                              void* d_out, int out_size)
{
    const float* x    = (const float*)d_in[0];
    const float* Wq   = (const float*)d_in[1];
    const float* bq   = (const float*)d_in[2];
    const float* Wk   = (const float*)d_in[3];
    const float* bk   = (const float*)d_in[4];
    const float* Wv   = (const float*)d_in[5];
    const float* bv   = (const float*)d_in[6];
    const float* temp = (const float*)d_in[7];
    float* out = (float*)d_out;

    dim3 blk(256);
    k_qkv    <<<dim3(DD / 128, M_TOT / 128, 3), blk>>>(x, Wq, bq, Wk, bk, Wv, bv);
    k_scores <<<dim3(SS / 128, SS / 128, BB),   blk>>>(temp);
    k_softmax<<<dim3(M_TOT),                    blk>>>();
    k_pv     <<<dim3(DD / 128, SS / 128, BB),   blk>>>(out);
    k_entmean<<<1, blk>>>(out, out_size);
}

// round 13
// speedup vs baseline: 3.2101x; 3.2101x over previous
#include <cuda_runtime.h>
#include <cuda_bf16.h>
#include <math.h>
#include <cstdint>

// Problem constants
#define BB 4
#define SS 2048
#define DD 1024
#define M_TOT (BB * SS)   // 8192

// ---------------- arena (single __device__ allocation, 204 MiB < 256 MiB) ----------------
static constexpr size_t SZ_HALF = (size_t)M_TOT * DD * 2;   // 16,777,216  (bf16 plane)
static constexpr size_t SZ_W    = (size_t)DD * DD * 2;      //  2,097,152
static constexpr size_t SZ_S    = (size_t)BB * SS * SS * 4; // 67,108,864  (fp32 scores)

static constexpr size_t OFF_XHI  = 0;
static constexpr size_t OFF_XLO  = OFF_XHI + SZ_HALF;
static constexpr size_t OFF_WQH  = OFF_XLO + SZ_HALF;
static constexpr size_t OFF_WQL  = OFF_WQH + SZ_W;
static constexpr size_t OFF_WKH  = OFF_WQL + SZ_W;
static constexpr size_t OFF_WKL  = OFF_WKH + SZ_W;
static constexpr size_t OFF_WVH  = OFF_WKL + SZ_W;
static constexpr size_t OFF_WVL  = OFF_WVH + SZ_W;
static constexpr size_t OFF_QHI  = OFF_WVL + SZ_W;
static constexpr size_t OFF_QLO  = OFF_QHI + SZ_HALF;
static constexpr size_t OFF_KHI  = OFF_QLO + SZ_HALF;
static constexpr size_t OFF_KLO  = OFF_KHI + SZ_HALF;
static constexpr size_t OFF_VTHI = OFF_KLO + SZ_HALF;
static constexpr size_t OFF_VTLO = OFF_VTHI + SZ_HALF;
static constexpr size_t OFF_S    = OFF_VTLO + SZ_HALF;     // scores fp32; P hi/lo in place later
static constexpr size_t OFF_ENT  = OFF_S + SZ_S;
static constexpr size_t ARENA_SZ = OFF_ENT + (size_t)M_TOT * 4;   // 213,942,272 B ~= 204 MiB

__device__ __align__(256) uint8_t g_arena[ARENA_SZ];

// ---------------- helpers ----------------
__device__ __forceinline__ uint32_t smem_to_u32(const void* p) {
    uint32_t a;
    asm("{ .reg .u64 t; cvta.to.shared.u64 t, %1; cvt.u32.u64 %0, t; }" : "=r"(a) : "l"(p));
    return a;
}
#define SW64(b) ((b) ^ (((b) >> 3) & 0x30))

#define CP_ASYNC16(dst, src) \
    asm volatile("cp.async.cg.shared.global [%0], [%1], 16;" :: "r"(dst), "l"(src))
#define CP_COMMIT()  asm volatile("cp.async.commit_group;" ::: "memory")
#define CP_WAIT0()   asm volatile("cp.async.wait_group 0;" ::: "memory")
#define CP_WAIT1()   asm volatile("cp.async.wait_group 1;" ::: "memory")

#define LDSM_X4(r, a) \
    asm volatile("ldmatrix.sync.aligned.m8n8.x4.shared.b16 {%0,%1,%2,%3}, [%4];" \
        : "=r"((r)[0]), "=r"((r)[1]), "=r"((r)[2]), "=r"((r)[3]) : "r"(a))

#define MMA16816(d, a, b0, b1) \
    asm volatile("mma.sync.aligned.m16n8k16.row.col.f32.bf16.bf16.f32 " \
        "{%0,%1,%2,%3}, {%4,%5,%6,%7}, {%8,%9}, {%0,%1,%2,%3};" \
        : "+f"((d)[0]), "+f"((d)[1]), "+f"((d)[2]), "+f"((d)[3]) \
        : "r"((a)[0]), "r"((a)[1]), "r"((a)[2]), "r"((a)[3]), "r"(b0), "r"(b1))

// ---------------- GEMM (mma.sync HMMA, bf16 hi/lo x3) ----------------
// CTA tile 128(M) x 64(N), K-chunk 32, static smem 48KB double-buffered.
// 8 warps in 4M x 2N, warp tile 32x32.
// MODE: 0=PROJ (bias[n], bf16 split out)  1=VT (bias[m], bf16 split out)
//       2=SCORES (alpha=0.125/temp, fp32 out)  3=PV (fp32 out)
static constexpr int STAGE = 24576;

template <int MODE>
__global__ __launch_bounds__(256) void gemm_mma(
    const __nv_bfloat16* __restrict__ Ahi, const __nv_bfloat16* __restrict__ Alo,
    int lda, size_t a_zoff,
    const __nv_bfloat16* __restrict__ Bhi, const __nv_bfloat16* __restrict__ Blo,
    int ldb, size_t b_zoff, int b_col_z,
    float* __restrict__ Cf, __nv_bfloat16* __restrict__ Chi, __nv_bfloat16* __restrict__ Clo,
    int ldc, size_t c_zoff,
    const float* __restrict__ bias, const float* __restrict__ temp, int ktot)
{
    __shared__ __align__(256) uint8_t tiles[2 * STAGE];
    const uint32_t TB = smem_to_u32(tiles);

    const int tid = threadIdx.x;
    const int wid = tid >> 5, lane = tid & 31;
    const int z = blockIdx.z;
    const int n0 = blockIdx.x * 64;
    const int m0 = blockIdx.y * 128;
    const int wm = (wid & 3) * 32;
    const int wn = (wid >> 2) * 32;

    const __nv_bfloat16* Ah = Ahi + (size_t)z * a_zoff;
    const __nv_bfloat16* Al = Alo + (size_t)z * a_zoff;
    const __nv_bfloat16* Bh = Bhi + (size_t)z * b_zoff;
    const __nv_bfloat16* Bl = Blo + (size_t)z * b_zoff;
    const int bco = z * b_col_z;

    float acc[2][4][4];
#pragma unroll
    for (int i = 0; i < 2; i++)
#pragma unroll
        for (int j = 0; j < 4; j++)
#pragma unroll
            for (int r = 0; r < 4; r++) acc[i][j][r] = 0.0f;

    const int nch = ktot >> 5;

    const int lr = tid >> 2;
    const int lc = (tid & 3) * 8;

#define LOAD_STAGE(ii, ss) do {                                                       \
    const int k0_ = (ii) << 5;                                                        \
    const uint32_t base_ = TB + (ss) * STAGE;                                         \
    _Pragma("unroll")                                                                 \
    for (int v = 0; v < 2; v++) {                                                     \
        const int r_ = lr + v * 64;                                                   \
        const uint32_t so_ = base_ + SW64(r_ * 64 + lc * 2);                          \
        const size_t goA_ = (size_t)(m0 + r_) * lda + k0_ + lc;                       \
        CP_ASYNC16(so_,         (const void*)(Ah + goA_));                            \
        CP_ASYNC16(so_ + 8192u, (const void*)(Al + goA_));                            \
    }                                                                                 \
    {                                                                                 \
        const uint32_t so_ = base_ + 16384u + SW64(lr * 64 + lc * 2);                 \
        const size_t goB_ = (size_t)(n0 + lr) * ldb + bco + k0_ + lc;                 \
        CP_ASYNC16(so_,         (const void*)(Bh + goB_));                            \
        CP_ASYNC16(so_ + 4096u, (const void*)(Bl + goB_));                            \
    }                                                                                 \
    CP_COMMIT();                                                                      \
} while (0)

    LOAD_STAGE(0, 0);

    const int g = lane >> 3, glr = lane & 7;
    const int a_row_off = (g & 1) * 8 + glr;
    const int a_col_off = (g >> 1) * 8;
    const int b_row_off = (g >> 1) * 8 + glr;
    const int b_col_off = (g & 1) * 8;

#pragma unroll 1
    for (int i = 0; i < nch; i++) {
        if (i + 1 < nch) { LOAD_STAGE(i + 1, (i + 1) & 1); CP_WAIT1(); }
        else             { CP_WAIT0(); }
        __syncthreads();

        const uint32_t base = TB + (i & 1) * STAGE;
#pragma unroll
        for (int kk = 0; kk < 2; kk++) {
            uint32_t ah[2][4], al[2][4];
            const int acol = kk * 16 + a_col_off;
#pragma unroll
            for (int mi = 0; mi < 2; mi++) {
                const int row = wm + mi * 16 + a_row_off;
                const uint32_t ad = base + SW64(row * 64 + acol * 2);
                LDSM_X4(ah[mi], ad);
                LDSM_X4(al[mi], ad + 8192u);
            }
            uint32_t bh[2][4], bl[2][4];
            const int bcol = kk * 16 + b_col_off;
#pragma unroll
            for (int ni = 0; ni < 2; ni++) {
                const int row = wn + ni * 16 + b_row_off;
                const uint32_t bd = base + 16384u + SW64(row * 64 + bcol * 2);
                LDSM_X4(bh[ni], bd);
                LDSM_X4(bl[ni], bd + 4096u);
            }
#pragma unroll
            for (int mi = 0; mi < 2; mi++)
#pragma unroll
                for (int nj = 0; nj < 4; nj++) {
                    const int ni = nj >> 1, hl = (nj & 1) * 2;
                    MMA16816(acc[mi][nj], ah[mi], bh[ni][hl], bh[ni][hl + 1]);
                    MMA16816(acc[mi][nj], ah[mi], bl[ni][hl], bl[ni][hl + 1]);
                    MMA16816(acc[mi][nj], al[mi], bh[ni][hl], bh[ni][hl + 1]);
                }
        }
        __syncthreads();
    }

    // ---- epilogue ----
    const int tr = lane >> 2;
    const int tc = (lane & 3) * 2;
    float alpha = 1.0f;
    if (MODE == 2) alpha = 0.125f / __ldg(temp);

    float* Cfo = (MODE >= 2) ? (Cf + (size_t)z * c_zoff) : nullptr;
    __nv_bfloat16* Ch = (MODE <= 1) ? (Chi + (size_t)z * c_zoff) : nullptr;
    __nv_bfloat16* Cl = (MODE <= 1) ? (Clo + (size_t)z * c_zoff) : nullptr;

#pragma unroll
    for (int mi = 0; mi < 2; mi++) {
        const int mlo = m0 + wm + mi * 16 + tr;
        const int mhi = mlo + 8;
#pragma unroll
        for (int nj = 0; nj < 4; nj++) {
            const int n = n0 + wn + nj * 8 + tc;
            float v0 = acc[mi][nj][0], v1 = acc[mi][nj][1];
            float v2 = acc[mi][nj][2], v3 = acc[mi][nj][3];
            if (MODE == 0) {
                const float b0 = bias[n], b1 = bias[n + 1];
                v0 += b0; v1 += b1; v2 += b0; v3 += b1;
            } else if (MODE == 1) {
                v0 += bias[mlo]; v1 += bias[mlo];
                v2 += bias[mhi]; v3 += bias[mhi];
            } else {
                v0 *= alpha; v1 *= alpha; v2 *= alpha; v3 *= alpha;
            }
            if (MODE <= 1) {
                __nv_bfloat16 h0 = __float2bfloat16(v0), h1 = __float2bfloat16(v1);
                __nv_bfloat16 h2 = __float2bfloat16(v2), h3 = __float2bfloat16(v3);
                __nv_bfloat162 hh0; hh0.x = h0; hh0.y = h1;
                __nv_bfloat162 hh1; hh1.x = h2; hh1.y = h3;
                __nv_bfloat162 ll0;
                ll0.x = __float2bfloat16(v0 - __bfloat162float(h0));
                ll0.y = __float2bfloat16(v1 - __bfloat162float(h1));
                __nv_bfloat162 ll1;
                ll1.x = __float2bfloat16(v2 - __bfloat162float(h2));
                ll1.y = __float2bfloat16(v3 - __bfloat162float(h3));
                *reinterpret_cast<__nv_bfloat162*>(Ch + (size_t)mlo * ldc + n) = hh0;
                *reinterpret_cast<__nv_bfloat162*>(Ch + (size_t)mhi * ldc + n) = hh1;
                *reinterpret_cast<__nv_bfloat162*>(Cl + (size_t)mlo * ldc + n) = ll0;
                *reinterpret_cast<__nv_bfloat162*>(Cl + (size_t)mhi * ldc + n) = ll1;
            } else {
                float2 f0; f0.x = v0; f0.y = v1;
                float2 f1; f1.x = v2; f1.y = v3;
                *reinterpret_cast<float2*>(Cfo + (size_t)mlo * ldc + n) = f0;
                *reinterpret_cast<float2*>(Cfo + (size_t)mhi * ldc + n) = f1;
            }
        }
    }
#undef LOAD_STAGE
}

// ---------------- conversion kernels ----------------
__global__ __launch_bounds__(256) void k_convx(const float* __restrict__ x) {
    __nv_bfloat16* xhi = (__nv_bfloat16*)(g_arena + OFF_XHI);
    __nv_bfloat16* xlo = (__nv_bfloat16*)(g_arena + OFF_XLO);
    const int idx = (blockIdx.x * 256 + threadIdx.x) * 4;
    const float4 v = *reinterpret_cast<const float4*>(x + idx);
    __nv_bfloat16 h[4], l[4];
    const float f[4] = {v.x, v.y, v.z, v.w};
#pragma unroll
    for (int j = 0; j < 4; j++) {
        h[j] = __float2bfloat16(f[j]);
        l[j] = __float2bfloat16(f[j] - __bfloat162float(h[j]));
    }
    __nv_bfloat162 hh0; hh0.x = h[0]; hh0.y = h[1];
    __nv_bfloat162 hh1; hh1.x = h[2]; hh1.y = h[3];
    __nv_bfloat162 ll0; ll0.x = l[0]; ll0.y = l[1];
    __nv_bfloat162 ll1; ll1.x = l[2]; ll1.y = l[3];
    *reinterpret_cast<__nv_bfloat162*>(xhi + idx) = hh0;
    *reinterpret_cast<__nv_bfloat162*>(xhi + idx + 2) = hh1;
    *reinterpret_cast<__nv_bfloat162*>(xlo + idx) = ll0;
    *reinterpret_cast<__nv_bfloat162*>(xlo + idx + 2) = ll1;
}

__global__ __launch_bounds__(256) void k_convw(const float* __restrict__ Wq,
                                               const float* __restrict__ Wk,
                                               const float* __restrict__ Wv) {
    __shared__ float t[32][33];
    const float* W = (blockIdx.z == 0) ? Wq : (blockIdx.z == 1) ? Wk : Wv;
    __nv_bfloat16* hi = (__nv_bfloat16*)(g_arena +
        ((blockIdx.z == 0) ? OFF_WQH : (blockIdx.z == 1) ? OFF_WKH : OFF_WVH));
    __nv_bfloat16* lo = (__nv_bfloat16*)(g_arena +
        ((blockIdx.z == 0) ? OFF_WQL : (blockIdx.z == 1) ? OFF_WKL : OFF_WVL));
    const int tx = threadIdx.x & 31, ty = (threadIdx.x >> 5);
#pragma unroll
    for (int j = 0; j < 4; j++) {
        const int k = blockIdx.y * 32 + ty + j * 8;
        t[ty + j * 8][tx] = W[(size_t)k * DD + blockIdx.x * 32 + tx];
    }
    __syncthreads();
#pragma unroll
    for (int j = 0; j < 4; j++) {
        const int n = blockIdx.x * 32 + ty + j * 8;
        const int k = blockIdx.y * 32 + tx;
        const float v = t[tx][ty + j * 8];
        const __nv_bfloat16 h = __float2bfloat16(v);
        hi[(size_t)n * DD + k] = h;
        lo[(size_t)n * DD + k] = __float2bfloat16(v - __bfloat162float(h));
    }
}

// ---------------- reductions / softmax ----------------
__device__ __forceinline__ float warp_sum(float v) {
#pragma unroll
    for (int o = 16; o; o >>= 1) v += __shfl_xor_sync(0xffffffffu, v, o);
    return v;
}
__device__ __forceinline__ float warp_max(float v) {
#pragma unroll
    for (int o = 16; o; o >>= 1) v = fmaxf(v, __shfl_xor_sync(0xffffffffu, v, o));
    return v;
}
__device__ __forceinline__ float block_sum(float v, float* sh) {
    const int lane = threadIdx.x & 31, w = threadIdx.x >> 5;
    v = warp_sum(v);
    if (lane == 0) sh[w] = v;
    __syncthreads();
    if (w == 0) {
        float r = (lane < 8) ? sh[lane] : 0.0f;
        r = warp_sum(r);
        if (lane == 0) sh[0] = r;
    }
    __syncthreads();
    float r = sh[0];
    __syncthreads();
    return r;
}
__device__ __forceinline__ float block_max(float v, float* sh) {
    const int lane = threadIdx.x & 31, w = threadIdx.x >> 5;
    v = warp_max(v);
    if (lane == 0) sh[w] = v;
    __syncthreads();
    if (w == 0) {
        float r = (lane < 8) ? sh[lane] : -INFINITY;
        r = warp_max(r);
        if (lane == 0) sh[0] = r;
    }
    __syncthreads();
    float r = sh[0];
    __syncthreads();
    return r;
}

// softmax + entropy; writes P bf16 hi/lo IN PLACE over the fp32 score row
// (8KB fp32 -> 4KB hi + 4KB lo). All reads complete before the reduction
// barriers; writes happen after them -> no WAR hazard.
__global__ __launch_bounds__(256) void k_softmax() {
    __shared__ float sh[8];
    const int row = blockIdx.x;
    float* s = (float*)(g_arena + OFF_S) + (size_t)row * SS;
    float* ent = (float*)(g_arena + OFF_ENT);
    const int tid = threadIdx.x;

    float v[8];
#pragma unroll
    for (int j = 0; j < 8; j++) v[j] = s[tid + j * 256];

    float mx = -INFINITY;
#pragma unroll
    for (int j = 0; j < 8; j++) mx = fmaxf(mx, v[j]);
    mx = block_max(mx, sh);

    float l = 0.0f, t = 0.0f;
#pragma unroll
    for (int j = 0; j < 8; j++) {
        float e = expf(v[j] - mx);
        l += e;
        t += e * v[j];
        v[j] = e;
    }
    l = block_sum(l, sh);
    t = block_sum(t, sh);
    const float inv = 1.0f / l;

    __nv_bfloat16* ph = (__nv_bfloat16*)s;        // first 4KB of row
    __nv_bfloat16* pl = (__nv_bfloat16*)s + SS;   // second 4KB
#pragma unroll
    for (int j = 0; j < 8; j++) {
        const float p = v[j] * inv;
        const __nv_bfloat16 h = __float2bfloat16(p);
        ph[tid + j * 256] = h;
        pl[tid + j * 256] = __float2bfloat16(p - __bfloat162float(h));
    }
    if (tid == 0) ent[row] = (mx + logf(l)) - t * inv;
}

__global__ __launch_bounds__(256) void k_entmean(float* __restrict__ out, int out_size) {
    __shared__ float sh[8];
    const float* ent = (const float*)(g_arena + OFF_ENT);
    float s = 0.0f;
    for (int i = threadIdx.x; i < M_TOT; i += 256) s += ent[i];
    s = block_sum(s, sh);
    if (threadIdx.x == 0) out[out_size - 1] = s * (1.0f / M_TOT);
}

// ---------------- launch ----------------
extern "C" void kernel_launch(void* const* d_in, const int* in_sizes, int n_in,
                              void* d_out, int out_size)
{
    const float* x    = (const float*)d_in[0];
    const float* Wq   = (const float*)d_in[1];
    const float* bq   = (const float*)d_in[2];
    const float* Wk   = (const float*)d_in[3];
    const float* bk   = (const float*)d_in[4];
    const float* Wv   = (const float*)d_in[5];
    const float* bv   = (const float*)d_in[6];
    const float* temp = (const float*)d_in[7];
    float* out = (float*)d_out;

    // arena base (immediate query; capture-legal, no allocation)
    uint8_t* base = nullptr;
    cudaGetSymbolAddress((void**)&base, g_arena);
    __nv_bfloat16* XHI  = (__nv_bfloat16*)(base + OFF_XHI);
    __nv_bfloat16* XLO  = (__nv_bfloat16*)(base + OFF_XLO);
    __nv_bfloat16* WQH  = (__nv_bfloat16*)(base + OFF_WQH);
    __nv_bfloat16* WQL  = (__nv_bfloat16*)(base + OFF_WQL);
    __nv_bfloat16* WKH  = (__nv_bfloat16*)(base + OFF_WKH);
    __nv_bfloat16* WKL  = (__nv_bfloat16*)(base + OFF_WKL);
    __nv_bfloat16* WVH  = (__nv_bfloat16*)(base + OFF_WVH);
    __nv_bfloat16* WVL  = (__nv_bfloat16*)(base + OFF_WVL);
    __nv_bfloat16* QHI  = (__nv_bfloat16*)(base + OFF_QHI);
    __nv_bfloat16* QLO  = (__nv_bfloat16*)(base + OFF_QLO);
    __nv_bfloat16* KHI  = (__nv_bfloat16*)(base + OFF_KHI);
    __nv_bfloat16* KLO  = (__nv_bfloat16*)(base + OFF_KLO);
    __nv_bfloat16* VTHI = (__nv_bfloat16*)(base + OFF_VTHI);
    __nv_bfloat16* VTLO = (__nv_bfloat16*)(base + OFF_VTLO);
    float*         Sf   = (float*)(base + OFF_S);
    __nv_bfloat16* PHI  = (__nv_bfloat16*)(base + OFF_S);        // after softmax, in place
    __nv_bfloat16* PLO  = (__nv_bfloat16*)(base + OFF_S) + SS;   // +2048 elements into row

    dim3 blk(256);

    // conversions
    k_convx<<<M_TOT * DD / 1024, blk>>>(x);
    k_convw<<<dim3(32, 32, 3), blk>>>(Wq, Wk, Wv);

    // Q = X Wq + bq  (M=8192, N=1024, K=1024)
    gemm_mma<0><<<dim3(16, 64), blk>>>(
        XHI, XLO, DD, 0,  WQH, WQL, DD, 0, 0,
        nullptr, QHI, QLO, DD, 0,  bq, nullptr, DD);
    // K = X Wk + bk
    gemm_mma<0><<<dim3(16, 64), blk>>>(
        XHI, XLO, DD, 0,  WKH, WKL, DD, 0, 0,
        nullptr, KHI, KLO, DD, 0,  bk, nullptr, DD);
    // V^T[d][token] (M=1024, N=8192, K=1024), bias per row
    gemm_mma<1><<<dim3(128, 8), blk>>>(
        WVH, WVL, DD, 0,  XHI, XLO, DD, 0, 0,
        nullptr, VTHI, VTLO, M_TOT, 0,  bv, nullptr, DD);
    // scores = (Q K^T) * 0.125 / temp  (per batch: 2048x2048, K=1024) -> fp32 S
    gemm_mma<2><<<dim3(32, 16, BB), blk>>>(
        QHI, QLO, DD, (size_t)SS * DD,  KHI, KLO, DD, (size_t)SS * DD, 0,
        Sf, nullptr, nullptr, SS, (size_t)SS * SS,  nullptr, temp, DD);
    // softmax + entropy + P -> bf16 hi/lo in place over S
    k_softmax<<<M_TOT, blk>>>();
    // O = P V  (per batch: 2048x1024, K=2048); P rows have stride 2*SS bf16 elements
    gemm_mma<3><<<dim3(16, 16, BB), blk>>>(
        PHI, PLO, 2 * SS, (size_t)SS * 2 * SS,  VTHI, VTLO, M_TOT, 0, SS,
        out, nullptr, nullptr, DD, (size_t)SS * DD,  nullptr, nullptr, SS);
    // entropy mean
    k_entmean<<<1, blk>>>(out, out_size);
}